// round 15
// baseline (speedup 1.0000x reference)
#include <cuda_runtime.h>

// out[b][j] = sum over pixels (y,x) of image b with (y & x) == j, j in [0,1024).
// bin j = ((y>>5)&(x>>5))<<5 | ((y&31)&(x&31)).
//
// Persistent static-stride version. Grid = 592 CTAs (one full wave at 4/SM),
// 4736 warp-slots. Unit = 16 rows x 128 cols; 32768 units; warp ws processes
// u = ws, ws+4736, ... (6-7 units each -> tail quantization ~1.2% vs 13.5%
// for the 2048-CTA wave grid). 8-row register ring with lookahead: while
// processing rows 8..15 of unit u, rows 0..7 of unit u+4736 are prefetched
// (base address is pure arithmetic -> loads issue across unit boundaries,
// MLP never drains). Last unit per warp uses a no-prefetch variant.
// Flush: 4 atomicAdds per lane per unit.

#define FULLMASK 0xffffffffu
#define NUM_UNITS 32768u
#define NUM_WSLOTS 4736u

__device__ __forceinline__ float shx(float v, int msk) {
    return __shfl_xor_sync(FULLMASK, v, msk);
}

template<int YLO>
__device__ __forceinline__ void proc_row(float4 v, int m,
                                         float& a0, float& a1, float& a2, float& a3) {
    constexpr int q  = YLO & 3;          // y bits 0,1
    constexpr int yh = (YLO >> 2) & 7;   // y bits 2,3,4
    float s0 = 0.f, s1 = 0.f, s2 = 0.f, s3 = 0.f;

    if constexpr (q == 0)      { s0 = (v.x + v.y) + (v.z + v.w); }
    else if constexpr (q == 1) { s0 = v.x + v.z;  s1 = v.y + v.w; }
    else if constexpr (q == 2) { s0 = v.x + v.y;  s2 = v.z + v.w; }
    else                       { s0 = v.x; s1 = v.y; s2 = v.z; s3 = v.w; }

    if constexpr ((yh & 1) == 0) {
        s0 += shx(s0, 1);
        if constexpr (q & 1)  s1 += shx(s1, 1);
        if constexpr (q & 2)  s2 += shx(s2, 1);
        if constexpr (q == 3) s3 += shx(s3, 1);
    }
    if constexpr ((yh & 2) == 0) {
        s0 += shx(s0, 2);
        if constexpr (q & 1)  s1 += shx(s1, 2);
        if constexpr (q & 2)  s2 += shx(s2, 2);
        if constexpr (q == 3) s3 += shx(s3, 2);
    }
    if constexpr ((yh & 4) == 0) {
        s0 += shx(s0, 4);
        if constexpr (q & 1)  s1 += shx(s1, 4);
        if constexpr (q & 2)  s2 += shx(s2, 4);
        if constexpr (q == 3) s3 += shx(s3, 4);
    }

    if ((m & ~yh & 7) == 0) {
        a0 += s0;
        if constexpr (q & 1)  a1 += s1;
        if constexpr (q & 2)  a2 += s2;
        if constexpr (q == 3) a3 += s3;
    }
}

__device__ __forceinline__ float4 ld_row(const float* __restrict__ p, int row, int lane) {
    return *reinterpret_cast<const float4*>(p + (size_t)row * 1024 + 4 * lane);
}

// One 16-row unit with 8-row lookahead. Rows i=0..15 have ylo = 16*P + i.
// Steps 0..7 prefetch rows 8..15 of this unit; steps 8..15 prefetch rows 0..7
// of the NEXT unit (nbase) unless LAST.
template<int P, bool LAST, int I>
__device__ __forceinline__ void unit_step(const float* __restrict__ base,
                                          const float* __restrict__ nbase,
                                          float4 (&v)[8], int lane, int m,
                                          float& a0, float& a1, float& a2, float& a3) {
    float4 nv;
    constexpr bool pf = (I < 8) || !LAST;
    if constexpr (I < 8)       nv = ld_row(base,  I + 8, lane);
    else if constexpr (!LAST)  nv = ld_row(nbase, I - 8, lane);
    proc_row<16 * P + I>(v[I & 7], m, a0, a1, a2, a3);
    if constexpr (pf) v[I & 7] = nv;
    if constexpr (I + 1 < 16)
        unit_step<P, LAST, I + 1>(base, nbase, v, lane, m, a0, a1, a2, a3);
}

template<int P, bool LAST>
__device__ __forceinline__ void do_unit(const float* __restrict__ base,
                                        const float* __restrict__ nbase,
                                        float4 (&v)[8], int lane, int m,
                                        float& a0, float& a1, float& a2, float& a3) {
    unit_step<P, LAST, 0>(base, nbase, v, lane, m, a0, a1, a2, a3);
}

__device__ __forceinline__ const float* unit_base(const float* __restrict__ M, unsigned u) {
    // b = u>>9, rg = (u>>3)&63 (rows [16rg,16rg+16)), wc = u&7 (cols [128wc,...))
    return M + ((size_t)(u >> 9) << 20) + ((size_t)((u >> 3) & 63) << 14) + (u & 7) * 128;
}

__global__ void __launch_bounds__(256, 4) CNNDST_bin_kernel(
        const float* __restrict__ M, float* __restrict__ out) {
    const int lane = threadIdx.x & 31;
    const int m    = lane & 7;
    const int t    = lane >> 3;

    unsigned u = blockIdx.x * 8u + (threadIdx.x >> 5);   // warp-slot id, < 4736
    const float* base = unit_base(M, u);

    float4 v[8];
    #pragma unroll
    for (int i = 0; i < 8; ++i) v[i] = ld_row(base, i, lane);

    for (;;) {
        const unsigned un  = u + NUM_WSLOTS;
        const bool last    = (un >= NUM_UNITS);
        const float* nbase = last ? base : unit_base(M, un);

        float a0 = 0.f, a1 = 0.f, a2 = 0.f, a3 = 0.f;
        const int P = (u >> 3) & 1;                      // row-group parity (ylo bit 4)
        if (last) {
            if (P) do_unit<1, true >(base, nbase, v, lane, m, a0, a1, a2, a3);
            else   do_unit<0, true >(base, nbase, v, lane, m, a0, a1, a2, a3);
        } else {
            if (P) do_unit<1, false>(base, nbase, v, lane, m, a0, a1, a2, a3);
            else   do_unit<0, false>(base, nbase, v, lane, m, a0, a1, a2, a3);
        }

        // Flush this unit's 4 bins per lane.
        const int R5 = ((u >> 3) & 63) >> 1;             // y>>5 for this unit
        const int x5 = 4 * (int)(u & 7) + t;             // x>>5 for this lane's tile
        const int hi = R5 & x5;
        float* o = out + ((size_t)(u >> 9) << 10) + (hi << 5) + (m << 2);
        atomicAdd(o + 0, a0);
        atomicAdd(o + 1, a1);
        atomicAdd(o + 2, a2);
        atomicAdd(o + 3, a3);

        if (last) break;
        u = un;
        base = nbase;
    }
}

__global__ void CNNDST_zero_kernel(float* __restrict__ out) {
    reinterpret_cast<float4*>(out)[blockIdx.x * 256 + threadIdx.x] =
        make_float4(0.f, 0.f, 0.f, 0.f);
}

extern "C" void kernel_launch(void* const* d_in, const int* in_sizes, int n_in,
                              void* d_out, int out_size) {
    const float* M = (const float*)d_in[0];   // (64, 1, 1024, 1024) float32
    float* out = (float*)d_out;               // (64, 1024) float32
    (void)in_sizes; (void)n_in; (void)out_size;

    CNNDST_zero_kernel<<<64, 256>>>(out);     // 65536 floats
    CNNDST_bin_kernel<<<592, 256>>>(M, out);
}

// round 17
// speedup vs baseline: 1.0775x; 1.0775x over previous
#include <cuda_runtime.h>

// out[b][j] = sum over pixels (y,x) of image b with (y & x) == j, j in [0,1024).
// bin j = ((y>>5)&(x>>5))<<5 | ((y&31)&(x&31)).
//
// Static straight-line grid (the only structure that ever won): 4096 CTAs =
// 64 images x 64 row-groups of 16 rows; 8 warps per CTA each own a
// 16-row x 128-col tile. 6.92 waves at 4 CTAs/SM -> tail quantization ~1.1%
// (vs 13.5% for the 32-row/2048-CTA version measured at DRAM 75.7%).
// Body: fully unrolled 16-row pipeline with 8-row register-ring lookahead
// (load row r+8 before processing row r). Two compile-time body variants by
// row-group parity (ylo bit 4); each ~6KB SASS, no I$ pressure.
// Flush: 4 atomicAdds per lane per CTA-warp.

#define FULLMASK 0xffffffffu

__device__ __forceinline__ float shx(float v, int msk) {
    return __shfl_xor_sync(FULLMASK, v, msk);
}

template<int YLO>
__device__ __forceinline__ void proc_row(float4 v, int m,
                                         float& a0, float& a1, float& a2, float& a3) {
    constexpr int q  = YLO & 3;          // y bits 0,1
    constexpr int yh = (YLO >> 2) & 7;   // y bits 2,3,4
    float s0 = 0.f, s1 = 0.f, s2 = 0.f, s3 = 0.f;

    // Reduce x bits 0,1 in-register: s[p] = sum of v[e] with (e & q) == p.
    if constexpr (q == 0)      { s0 = (v.x + v.y) + (v.z + v.w); }
    else if constexpr (q == 1) { s0 = v.x + v.z;  s1 = v.y + v.w; }
    else if constexpr (q == 2) { s0 = v.x + v.y;  s2 = v.z + v.w; }
    else                       { s0 = v.x; s1 = v.y; s2 = v.z; s3 = v.w; }

    // Butterfly-reduce x bits 2..4 across lanes where the y bit is 0.
    if constexpr ((yh & 1) == 0) {
        s0 += shx(s0, 1);
        if constexpr (q & 1)  s1 += shx(s1, 1);
        if constexpr (q & 2)  s2 += shx(s2, 1);
        if constexpr (q == 3) s3 += shx(s3, 1);
    }
    if constexpr ((yh & 2) == 0) {
        s0 += shx(s0, 2);
        if constexpr (q & 1)  s1 += shx(s1, 2);
        if constexpr (q & 2)  s2 += shx(s2, 2);
        if constexpr (q == 3) s3 += shx(s3, 2);
    }
    if constexpr ((yh & 4) == 0) {
        s0 += shx(s0, 4);
        if constexpr (q & 1)  s1 += shx(s1, 4);
        if constexpr (q & 2)  s2 += shx(s2, 4);
        if constexpr (q == 3) s3 += shx(s3, 4);
    }

    // Lane m is the canonical owner iff m is a subset of yh.
    if ((m & ~yh & 7) == 0) {
        a0 += s0;
        if constexpr (q & 1)  a1 += s1;
        if constexpr (q & 2)  a2 += s2;
        if constexpr (q == 3) a3 += s3;
    }
}

__device__ __forceinline__ float4 ld_row(const float* __restrict__ p, int row, int lane) {
    return *reinterpret_cast<const float4*>(p + (size_t)row * 1024 + 4 * lane);
}

// 16-row pipelined body, rows i = 0..15, ylo = 16*P + i.
// Steps 0..7 prefetch rows 8..15; steps 8..15 drain the ring.
template<int P, int I>
__device__ __forceinline__ void step16(const float* __restrict__ base,
                                       float4 (&v)[8], int lane, int m,
                                       float& a0, float& a1, float& a2, float& a3) {
    float4 nv;
    if constexpr (I < 8) nv = ld_row(base, I + 8, lane);
    proc_row<16 * P + I>(v[I & 7], m, a0, a1, a2, a3);
    if constexpr (I < 8) v[I & 7] = nv;
    if constexpr (I + 1 < 16)
        step16<P, I + 1>(base, v, lane, m, a0, a1, a2, a3);
}

__global__ void __launch_bounds__(256, 4) CNNDST_bin_kernel(
        const float* __restrict__ M, float* __restrict__ out) {
    const int blk  = blockIdx.x;       // 4096 = 64 images * 64 row-groups
    const int b    = blk >> 6;         // image
    const int g    = blk & 63;         // row-group: rows [16g, 16g+16)
    const int w    = threadIdx.x >> 5; // warp 0..7 -> cols [128w, 128w+128)
    const int lane = threadIdx.x & 31;
    const int m    = lane & 7;

    const float* base = M + ((size_t)b << 20) + ((size_t)g << 14) + w * 128;

    float4 v[8];
    #pragma unroll
    for (int i = 0; i < 8; ++i) v[i] = ld_row(base, i, lane);

    float a0 = 0.f, a1 = 0.f, a2 = 0.f, a3 = 0.f;
    if (g & 1) step16<1, 0>(base, v, lane, m, a0, a1, a2, a3);
    else       step16<0, 0>(base, v, lane, m, a0, a1, a2, a3);

    const int t  = lane >> 3;             // column-tile within warp slice
    const int hi = (g >> 1) & (4 * w + t);// (y>>5) & (x>>5)
    float* o = out + ((size_t)b << 10) + (hi << 5) + (m << 2);
    atomicAdd(o + 0, a0);
    atomicAdd(o + 1, a1);
    atomicAdd(o + 2, a2);
    atomicAdd(o + 3, a3);
}

__global__ void CNNDST_zero_kernel(float* __restrict__ out) {
    reinterpret_cast<float4*>(out)[blockIdx.x * 256 + threadIdx.x] =
        make_float4(0.f, 0.f, 0.f, 0.f);
}

extern "C" void kernel_launch(void* const* d_in, const int* in_sizes, int n_in,
                              void* d_out, int out_size) {
    const float* M = (const float*)d_in[0];   // (64, 1, 1024, 1024) float32
    float* out = (float*)d_out;               // (64, 1024) float32
    (void)in_sizes; (void)n_in; (void)out_size;

    CNNDST_zero_kernel<<<64, 256>>>(out);     // 65536 floats
    CNNDST_bin_kernel<<<4096, 256>>>(M, out);
}